// round 1
// baseline (speedup 1.0000x reference)
#include <cuda_runtime.h>

// MPSLayer: out[b,:] = (prod_t x[b,t]) * (1^T * A_0*...*A_{D-1} * P) + bias
// Factorization is exact up to fp32 rounding; both sides underflow to exactly 0
// for the given input distribution, guarded so 0 * huge never makes a NaN.

#define R  16
#define RR 256
#define CHUNK 32
#define MAX_CHUNKS 256

__device__ float g_part[MAX_CHUNKS * RR];  // partial chain products
__device__ float g_w[4096];                // w vector (O elements)

// K1: each block computes the ordered product of CHUNK consecutive core matrices.
__global__ void chain_partial(const float* __restrict__ cores, int D) {
    __shared__ float M[RR];
    __shared__ float Bm[RR];
    const int t = threadIdx.x;           // 0..255
    const int i = t >> 4, j = t & 15;
    const int g = blockIdx.x;
    const int start = g * CHUNK;
    const int end   = min(start + CHUNK, D);

    M[t] = cores[(size_t)start * RR + t];
    __syncthreads();
    for (int s = start + 1; s < end; ++s) {
        Bm[t] = cores[(size_t)s * RR + t];
        __syncthreads();
        float acc = 0.0f;
#pragma unroll
        for (int k = 0; k < R; ++k)
            acc = fmaf(M[i * R + k], Bm[k * R + j], acc);
        __syncthreads();
        M[t] = acc;
        __syncthreads();
    }
    g_part[g * RR + t] = M[t];
}

// K2: product of the nchunks partials (in order), then w = 1^T * M * proj.
__global__ void chain_final(const float* __restrict__ proj, int nchunks, int O) {
    __shared__ float M[RR];
    __shared__ float Bm[RR];
    __shared__ float u[R];
    const int t = threadIdx.x;
    const int i = t >> 4, j = t & 15;

    M[t] = g_part[t];
    __syncthreads();
    for (int s = 1; s < nchunks; ++s) {
        Bm[t] = g_part[s * RR + t];
        __syncthreads();
        float acc = 0.0f;
#pragma unroll
        for (int k = 0; k < R; ++k)
            acc = fmaf(M[i * R + k], Bm[k * R + j], acc);
        __syncthreads();
        M[t] = acc;
        __syncthreads();
    }
    // u[j] = sum_i M[i][j]  (ones boundary vector)
    if (t < R) {
        float s = 0.0f;
#pragma unroll
        for (int ii = 0; ii < R; ++ii) s += M[ii * R + t];
        u[t] = s;
    }
    __syncthreads();
    // w[o] = sum_j u[j] * proj[j][o]
    for (int o = t; o < O; o += blockDim.x) {
        float s = 0.0f;
#pragma unroll
        for (int jj = 0; jj < R; ++jj)
            s = fmaf(u[jj], proj[jj * O + o], s);
        g_w[o] = s;
    }
}

// K3: one warp per batch row: p[b] = prod_t x[b,t]; out = p*w + bias (guarded).
__global__ void mps_main(const float* __restrict__ x,
                         const float* __restrict__ bias,
                         float* __restrict__ out,
                         int B, int D, int O) {
    const int warp = (blockIdx.x * blockDim.x + threadIdx.x) >> 5;
    const int lane = threadIdx.x & 31;
    if (warp >= B) return;

    const float* xr = x + (size_t)warp * D;
    float p = 1.0f;

    const int d4 = D >> 2;
    const float4* xr4 = (const float4*)xr;
    for (int idx = lane; idx < d4; idx += 32) {
        float4 v = xr4[idx];
        p *= v.x * v.y * v.z * v.w;
    }
    for (int idx = d4 * 4 + lane; idx < D; idx += 32)
        p *= xr[idx];

#pragma unroll
    for (int off = 16; off; off >>= 1)
        p *= __shfl_xor_sync(0xffffffffu, p, off);

    float* orow = out + (size_t)warp * O;
    if (p == 0.0f) {
        for (int o = lane; o < O; o += 32) orow[o] = bias[o];
    } else {
        for (int o = lane; o < O; o += 32)
            orow[o] = fmaf(p, g_w[o], bias[o]);
    }
}

extern "C" void kernel_launch(void* const* d_in, const int* in_sizes, int n_in,
                              void* d_out, int out_size) {
    const float* x     = (const float*)d_in[0];  // (B, D)
    const float* cores = (const float*)d_in[1];  // (D, 16, 16)
    const float* proj  = (const float*)d_in[2];  // (16, O)
    const float* bias  = (const float*)d_in[3];  // (O,)
    float* out = (float*)d_out;                  // (B, O)

    const int D = in_sizes[1] / RR;
    const int B = in_sizes[0] / D;
    const int O = in_sizes[3];

    int nchunks = (D + CHUNK - 1) / CHUNK;       // 64 for D=2048
    if (nchunks > MAX_CHUNKS) nchunks = MAX_CHUNKS;  // (not hit for this problem)

    chain_partial<<<nchunks, 256>>>(cores, D);
    chain_final<<<1, 256>>>(proj, nchunks, O);

    const int warpsPerBlock = 8;
    const int blocks = (B + warpsPerBlock - 1) / warpsPerBlock;
    mps_main<<<blocks, warpsPerBlock * 32>>>(x, bias, out, B, D, O);
}

// round 2
// speedup vs baseline: 1.9374x; 1.9374x over previous
#include <cuda_runtime.h>

// MPSLayer factored form:
//   out[b,:] = (prod_t x[b,t]) * (1^T * A_0*...*A_{D-1} * P) + bias
// Chain product computed as a 3-level parallel tree with all operands
// prefetched to shared (no global latency inside the sequential loops).

#define R   16
#define RR  256
#define TSTRIDE 20   // padded row stride for transposed B tiles (bank-conflict-light)

__device__ float g_part1[256 * RR];
__device__ float g_part2[16 * RR];
__device__ float g_w[4096];

// Multiply 'chunk' (<=16) consecutive matrices from src, write one matrix to dst[blockIdx].
__global__ void chain_stage(const float* __restrict__ src, float* __restrict__ dst,
                            int count, int chunk) {
    __shared__ __align__(16) float S[16][16 * TSTRIDE];  // transposed B tiles
    __shared__ __align__(16) float M[2][RR];             // double-buffered running product
    const int t = threadIdx.x;            // 0..255
    const int i = t >> 4, j = t & 15;
    const int start = blockIdx.x * chunk;
    const int end   = min(start + chunk, count);
    const int n     = end - start;

    // Prefetch matrices 1..n-1 transposed: S[s][j*TSTRIDE + k] = B_s[k][j]
    for (int s = 1; s < n; ++s)
        S[s][(t & 15) * TSTRIDE + (t >> 4)] = src[(size_t)(start + s) * RR + t];
    M[0][t] = src[(size_t)start * RR + t];
    __syncthreads();

    int cur = 0;
    for (int s = 1; s < n; ++s) {
        const float4* mrow = (const float4*)&M[cur][i * R];
        const float4* bcol = (const float4*)&S[s][j * TSTRIDE];
        float4 a0 = mrow[0], a1 = mrow[1], a2 = mrow[2], a3 = mrow[3];
        float4 b0 = bcol[0], b1 = bcol[1], b2 = bcol[2], b3 = bcol[3];
        float acc;
        acc = a0.x * b0.x;
        acc = fmaf(a0.y, b0.y, acc); acc = fmaf(a0.z, b0.z, acc); acc = fmaf(a0.w, b0.w, acc);
        acc = fmaf(a1.x, b1.x, acc); acc = fmaf(a1.y, b1.y, acc);
        acc = fmaf(a1.z, b1.z, acc); acc = fmaf(a1.w, b1.w, acc);
        acc = fmaf(a2.x, b2.x, acc); acc = fmaf(a2.y, b2.y, acc);
        acc = fmaf(a2.z, b2.z, acc); acc = fmaf(a2.w, b2.w, acc);
        acc = fmaf(a3.x, b3.x, acc); acc = fmaf(a3.y, b3.y, acc);
        acc = fmaf(a3.z, b3.z, acc); acc = fmaf(a3.w, b3.w, acc);
        M[cur ^ 1][t] = acc;
        cur ^= 1;
        __syncthreads();
    }
    dst[(size_t)blockIdx.x * RR + t] = M[cur][t];
}

// Final: product of n (<=16) partials in g_part2, then w = 1^T * M * proj.
__global__ void chain_final(const float* __restrict__ proj, int n, int O) {
    __shared__ __align__(16) float S[16][16 * TSTRIDE];
    __shared__ __align__(16) float M[2][RR];
    __shared__ float u[R];
    const int t = threadIdx.x;
    const int i = t >> 4, j = t & 15;

    for (int s = 1; s < n; ++s)
        S[s][(t & 15) * TSTRIDE + (t >> 4)] = g_part2[s * RR + t];
    M[0][t] = g_part2[t];
    __syncthreads();

    int cur = 0;
    for (int s = 1; s < n; ++s) {
        const float4* mrow = (const float4*)&M[cur][i * R];
        const float4* bcol = (const float4*)&S[s][j * TSTRIDE];
        float4 a0 = mrow[0], a1 = mrow[1], a2 = mrow[2], a3 = mrow[3];
        float4 b0 = bcol[0], b1 = bcol[1], b2 = bcol[2], b3 = bcol[3];
        float acc;
        acc = a0.x * b0.x;
        acc = fmaf(a0.y, b0.y, acc); acc = fmaf(a0.z, b0.z, acc); acc = fmaf(a0.w, b0.w, acc);
        acc = fmaf(a1.x, b1.x, acc); acc = fmaf(a1.y, b1.y, acc);
        acc = fmaf(a1.z, b1.z, acc); acc = fmaf(a1.w, b1.w, acc);
        acc = fmaf(a2.x, b2.x, acc); acc = fmaf(a2.y, b2.y, acc);
        acc = fmaf(a2.z, b2.z, acc); acc = fmaf(a2.w, b2.w, acc);
        acc = fmaf(a3.x, b3.x, acc); acc = fmaf(a3.y, b3.y, acc);
        acc = fmaf(a3.z, b3.z, acc); acc = fmaf(a3.w, b3.w, acc);
        M[cur ^ 1][t] = acc;
        cur ^= 1;
        __syncthreads();
    }

    if (t < R) {
        float s = 0.0f;
#pragma unroll
        for (int ii = 0; ii < R; ++ii) s += M[cur][ii * R + t];
        u[t] = s;
    }
    __syncthreads();
    for (int o = t; o < O; o += blockDim.x) {
        float s = 0.0f;
#pragma unroll
        for (int k = 0; k < R; ++k)
            s = fmaf(u[k], proj[k * O + o], s);
        g_w[o] = s;
    }
}

// One warp per batch row: p[b] = prod_t x[b,t]; out = p*w + bias (guarded).
__global__ void mps_main(const float* __restrict__ x,
                         const float* __restrict__ bias,
                         float* __restrict__ out,
                         int B, int D, int O) {
    const int warp = (blockIdx.x * blockDim.x + threadIdx.x) >> 5;
    const int lane = threadIdx.x & 31;
    if (warp >= B) return;

    const float* xr = x + (size_t)warp * D;
    float p = 1.0f;

    const int d4 = D >> 2;
    const float4* xr4 = (const float4*)xr;
#pragma unroll 8
    for (int idx = lane; idx < d4; idx += 32) {
        float4 v = xr4[idx];
        p *= v.x * v.y * v.z * v.w;
    }
    for (int idx = d4 * 4 + lane; idx < D; idx += 32)
        p *= xr[idx];

#pragma unroll
    for (int off = 16; off; off >>= 1)
        p *= __shfl_xor_sync(0xffffffffu, p, off);

    float* orow = out + (size_t)warp * O;
    if (p == 0.0f) {
        for (int o = lane; o < O; o += 32) orow[o] = bias[o];
    } else {
        for (int o = lane; o < O; o += 32)
            orow[o] = fmaf(p, g_w[o], bias[o]);
    }
}

extern "C" void kernel_launch(void* const* d_in, const int* in_sizes, int n_in,
                              void* d_out, int out_size) {
    const float* x     = (const float*)d_in[0];  // (B, D)
    const float* cores = (const float*)d_in[1];  // (D, 16, 16)
    const float* proj  = (const float*)d_in[2];  // (16, O)
    const float* bias  = (const float*)d_in[3];  // (O,)
    float* out = (float*)d_out;                  // (B, O)

    const int D = in_sizes[1] / RR;
    const int B = in_sizes[0] / D;
    const int O = in_sizes[3];

    // 3-level tree: D -> n1 -> n2 -> 1   (D=2048: 128 -> 8 -> 1)
    const int n1 = (D  + 15) / 16;
    const int n2 = (n1 + 15) / 16;

    float* p1; cudaGetSymbolAddress((void**)&p1, g_part1);
    float* p2; cudaGetSymbolAddress((void**)&p2, g_part2);

    chain_stage<<<n1, 256>>>(cores, p1, D, 16);
    chain_stage<<<n2, 256>>>(p1, p2, n1, 16);
    chain_final<<<1, 256>>>(proj, n2, O);

    const int warpsPerBlock = 8;
    const int blocks = (B + warpsPerBlock - 1) / warpsPerBlock;
    mps_main<<<blocks, warpsPerBlock * 32>>>(x, bias, out, B, D, O);
}